// round 5
// baseline (speedup 1.0000x reference)
#include <cuda_runtime.h>
#include <cstdint>

#define THREADS 256
#define EPS 1e-5f
#define GS 132
#define SM_A    0
#define SM_B    131072
#define SM_PAR  147456
#define SM_GBUF 156160
#define SMEM_BYTES 223744

__device__ float g_Wt[5 * 32768];

static __device__ __forceinline__ uint32_t s2u(const void* p) {
    uint32_t a;
    asm("{.reg .u64 t; cvta.to.shared.u64 t,%1; cvt.u32.u64 %0,t;}" : "=r"(a) : "l"(p));
    return a;
}
static __device__ __forceinline__ float rna(float x) {
    uint32_t r;
    asm("cvt.rna.tf32.f32 %0,%1;" : "=r"(r) : "f"(x));
    return __uint_as_float(r);
}
static __device__ __forceinline__ float sigm(float x) { return 1.f / (1.f + __expf(-x)); }
static __device__ __forceinline__ float tanh_(float x) { return 2.f / (1.f + __expf(-2.f * x)) - 1.f; }
static __device__ __forceinline__ void cp16(uint32_t dst, const void* src) {
    asm volatile("cp.async.cg.shared.global [%0],[%1],16;" :: "r"(dst), "l"(src));
}
#define CP_COMMIT() asm volatile("cp.async.commit_group;" ::: "memory")
#define CP_WAIT1()  asm volatile("cp.async.wait_group 1;" ::: "memory")
#define CP_WAIT0()  asm volatile("cp.async.wait_group 0;" ::: "memory")

static __device__ __forceinline__ void mma8(float* d, const uint32_t* a, const uint32_t* b) {
    asm volatile(
        "mma.sync.aligned.m16n8k8.row.col.f32.tf32.tf32.f32 "
        "{%0,%1,%2,%3},{%4,%5,%6,%7},{%8,%9},{%0,%1,%2,%3};"
        : "+f"(d[0]), "+f"(d[1]), "+f"(d[2]), "+f"(d[3])
        : "r"(a[0]), "r"(a[1]), "r"(a[2]), "r"(a[3]), "r"(b[0]), "r"(b[1]));
}

// g_Wt[g][s][t*2+h][lane]:  value = W_cat[k][n],  k = s*8 + (lane&3) + h*4,  n = g*128 + t*8 + (lane>>2)
__global__ void prep_kernel(const float* __restrict__ Wl, const float* __restrict__ Wr) {
    int gid = blockIdx.x * 256 + threadIdx.x;
    int g = gid >> 15, rem = gid & 32767;
    int s = rem >> 10, idx = (rem >> 5) & 31, l = rem & 31;
    int t = idx >> 1, h = idx & 1;
    int k = s * 8 + (l & 3) + h * 4;
    int n = g * 128 + t * 8 + (l >> 2);
    float w = (k < 128) ? Wl[k * 640 + n] : Wr[(k - 128) * 640 + n];
    g_Wt[gid] = rna(w);
}

__global__ void __launch_bounds__(THREADS, 1)
lstm_kernel(const float* __restrict__ lh, const float* __restrict__ lcell,
            const float* __restrict__ rh, const float* __restrict__ rcell,
            const float* __restrict__ br,
            const float* __restrict__ gu, const float* __restrict__ bu,
            const float* __restrict__ gi, const float* __restrict__ bi,
            const float* __restrict__ go, const float* __restrict__ bo,
            const float* __restrict__ glf, const float* __restrict__ blf,
            const float* __restrict__ grf, const float* __restrict__ brf,
            const float* __restrict__ gcc, const float* __restrict__ bcc,
            float* __restrict__ outh, float* __restrict__ outc) {
    extern __shared__ char sm[];
    float* smA  = (float*)(sm + SM_A);
    float* smB  = (float*)(sm + SM_B);
    float* brs  = (float*)(sm + SM_PAR);
    float* gsv  = brs + 640;
    float* bsv  = gsv + 768;
    float* gbuf = (float*)(sm + SM_GBUF);
    const uint32_t smBu = s2u(smB);
    const int tid = threadIdx.x, lane = tid & 31, wid = tid >> 5;
    const int mc = wid & 3, nh = wid >> 2;
    const int tile = blockIdx.x;

    // ---- stage params ----
    for (int i = tid; i < 640; i += THREADS) brs[i] = br[i];
    if (tid < 128) {
        gsv[tid] = gu[tid];        bsv[tid] = bu[tid];
        gsv[128 + tid] = gi[tid];  bsv[128 + tid] = bi[tid];
        gsv[256 + tid] = go[tid];  bsv[256 + tid] = bo[tid];
        gsv[384 + tid] = glf[tid]; bsv[384 + tid] = blf[tid];
        gsv[512 + tid] = grf[tid]; bsv[512 + tid] = brf[tid];
        gsv[640 + tid] = gcc[tid]; bsv[640 + tid] = bcc[tid];
    }
    // ---- stage A = [lh | rh] in mma A-fragment order: smA[((s*8+mt)*32 + lane)*4 + j] ----
    for (int i = tid; i < 8192; i += THREADS) {
        int r = i >> 6, q = i & 63;
        size_t base = (size_t)(tile * 128 + r) * 128;
        float4 v = (q < 32) ? ((const float4*)(lh + base))[q] : ((const float4*)(rh + base))[q - 32];
        float vv[4] = {rna(v.x), rna(v.y), rna(v.z), rna(v.w)};
        int rl = r & 15, mt = r >> 4;
        #pragma unroll
        for (int e = 0; e < 4; e++) {
            int k = q * 4 + e, s = k >> 3, kk = k & 7;
            int ln = (rl & 7) * 4 + (kk & 3);
            int j = (rl >> 3) + ((kk >> 2) << 1);
            smA[((s * 8 + mt) * 32 + ln) * 4 + j] = vv[e];
        }
    }
    __syncthreads();

    const int erow = tid >> 1, eh = tid & 1;
    const size_t erbase = (size_t)(tile * 128 + erow) * 128 + eh * 64;
    float creg[64];
    const int WGm[5] = {0, 1, 3, 4, 2};   // process order u,i,lf,rf,o -> weight/param index

    for (int pg = 0; pg < 5; pg++) {
        const int wg = WGm[pg];
        float acc[2][8][4];
        #pragma unroll
        for (int m2 = 0; m2 < 2; m2++)
            #pragma unroll
            for (int t2 = 0; t2 < 8; t2++)
                #pragma unroll
                for (int e = 0; e < 4; e++) acc[m2][t2][e] = 0.f;

        // preload chunk 0 (2 k-steps = 8 KB)
        {
            const float4* src = (const float4*)(g_Wt + wg * 32768) + tid * 2;
            cp16(smBu + tid * 32, src); cp16(smBu + tid * 32 + 16, src + 1);
            CP_COMMIT();
        }
        for (int c = 0; c < 16; c++) {
            if (c + 1 < 16) {
                const float4* src = (const float4*)(g_Wt + wg * 32768 + (c + 1) * 2048) + tid * 2;
                uint32_t d = smBu + ((c + 1) & 1) * 8192 + tid * 32;
                cp16(d, src); cp16(d + 16, src + 1);
                CP_COMMIT();
                CP_WAIT1();
            } else {
                CP_WAIT0();
            }
            __syncthreads();
            const float* bb = smB + (c & 1) * 2048;
            #pragma unroll
            for (int si = 0; si < 2; si++) {
                int s = c * 2 + si;
                uint32_t a[2][4];
                #pragma unroll
                for (int m2 = 0; m2 < 2; m2++) {
                    float4 av = *(const float4*)(smA + ((s * 8 + mc * 2 + m2) * 32 + lane) * 4);
                    a[m2][0] = __float_as_uint(av.x); a[m2][1] = __float_as_uint(av.y);
                    a[m2][2] = __float_as_uint(av.z); a[m2][3] = __float_as_uint(av.w);
                }
                uint32_t b[8][2];
                #pragma unroll
                for (int t2 = 0; t2 < 8; t2++) {
                    int idx = (nh * 8 + t2) * 2;
                    b[t2][0] = __float_as_uint(bb[si * 1024 + idx * 32 + lane]);
                    b[t2][1] = __float_as_uint(bb[si * 1024 + (idx + 1) * 32 + lane]);
                }
                #pragma unroll
                for (int m2 = 0; m2 < 2; m2++)
                    #pragma unroll
                    for (int t2 = 0; t2 < 8; t2++)
                        mma8(acc[m2][t2], a[m2], b[t2]);
            }
            __syncthreads();
        }
        // ---- fragments (+bias) -> gbuf ----
        #pragma unroll
        for (int m2 = 0; m2 < 2; m2++) {
            int r0 = mc * 32 + m2 * 16 + (lane >> 2);
            #pragma unroll
            for (int t2 = 0; t2 < 8; t2++) {
                int c0 = nh * 64 + t2 * 8 + 2 * (lane & 3);
                gbuf[r0 * GS + c0]           = acc[m2][t2][0] + brs[wg * 128 + c0];
                gbuf[r0 * GS + c0 + 1]       = acc[m2][t2][1] + brs[wg * 128 + c0 + 1];
                gbuf[(r0 + 8) * GS + c0]     = acc[m2][t2][2] + brs[wg * 128 + c0];
                gbuf[(r0 + 8) * GS + c0 + 1] = acc[m2][t2][3] + brs[wg * 128 + c0 + 1];
            }
        }
        __syncthreads();
        // ---- per-row LayerNorm + activation + running cell update ----
        float s1 = 0.f, s2 = 0.f;
        #pragma unroll
        for (int i = 0; i < 16; i++) {
            float4 v = *(const float4*)(gbuf + erow * GS + eh * 64 + i * 4);
            s1 += v.x + v.y + v.z + v.w;
            s2 += v.x * v.x + v.y * v.y + v.z * v.z + v.w * v.w;
        }
        s1 += __shfl_xor_sync(0xffffffffu, s1, 1);
        s2 += __shfl_xor_sync(0xffffffffu, s2, 1);
        float mu = s1 * 0.0078125f;
        float rsd = rsqrtf(fmaxf(s2 * 0.0078125f - mu * mu, 0.f) + EPS);
        const float* cellp = (pg == 2) ? lcell : rcell;
        #pragma unroll
        for (int i = 0; i < 16; i++) {
            float4 v = *(const float4*)(gbuf + erow * GS + eh * 64 + i * 4);
            float xv[4] = {v.x, v.y, v.z, v.w};
            float cvv[4] = {0.f, 0.f, 0.f, 0.f};
            if (pg == 2 || pg == 3) {
                float4 cv = *(const float4*)(cellp + erbase + i * 4);
                cvv[0] = cv.x; cvv[1] = cv.y; cvv[2] = cv.z; cvv[3] = cv.w;
            }
            #pragma unroll
            for (int e = 0; e < 4; e++) {
                int col = eh * 64 + i * 4 + e;
                float x = (xv[e] - mu) * rsd * gsv[wg * 128 + col] + bsv[wg * 128 + col];
                int ci = i * 4 + e;
                if (pg == 0)      creg[ci] = tanh_(x);
                else if (pg == 1) creg[ci] *= sigm(x);
                else if (pg == 2) creg[ci] += sigm(x) * cvv[e];
                else if (pg == 3) creg[ci] += sigm(x) * cvv[e];
                else              gbuf[erow * GS + col] = sigm(x);   // o activation in place
            }
        }
        __syncthreads();
    }

    // ---- final: LN(cell), h = sigm(o) * tanh(ln_c) ----
    float s1 = 0.f, s2 = 0.f;
    #pragma unroll
    for (int ci = 0; ci < 64; ci++) { s1 += creg[ci]; s2 += creg[ci] * creg[ci]; }
    s1 += __shfl_xor_sync(0xffffffffu, s1, 1);
    s2 += __shfl_xor_sync(0xffffffffu, s2, 1);
    float muc = s1 * 0.0078125f;
    float rsc = rsqrtf(fmaxf(s2 * 0.0078125f - muc * muc, 0.f) + EPS);
    #pragma unroll
    for (int i = 0; i < 16; i++) {
        float4 ho, co;
        float t[4];
        #pragma unroll
        for (int e = 0; e < 4; e++) {
            int col = eh * 64 + i * 4 + e;
            float cl = (creg[i * 4 + e] - muc) * rsc * gsv[640 + col] + bsv[640 + col];
            t[e] = cl;
            ((float*)&ho)[e] = gbuf[erow * GS + col] * tanh_(cl);
        }
        co.x = t[0]; co.y = t[1]; co.z = t[2]; co.w = t[3];
        *(float4*)(outh + erbase + i * 4) = ho;
        *(float4*)(outc + erbase + i * 4) = co;
    }
}

extern "C" void kernel_launch(void* const* d_in, const int* in_sizes, int n_in,
                              void* d_out, int out_size) {
    const float* lh = (const float*)d_in[0];
    const float* lc = (const float*)d_in[1];
    const float* rh = (const float*)d_in[2];
    const float* rc = (const float*)d_in[3];
    const float* Wl = (const float*)d_in[4];
    const float* Wr = (const float*)d_in[5];
    const float* br = (const float*)d_in[6];
    float* outh = (float*)d_out;
    float* outc = outh + (size_t)131072 * 128;
    cudaFuncSetAttribute(lstm_kernel, cudaFuncAttributeMaxDynamicSharedMemorySize, SMEM_BYTES);
    prep_kernel<<<640, 256>>>(Wl, Wr);
    lstm_kernel<<<1024, THREADS, SMEM_BYTES>>>(
        lh, lc, rh, rc, br,
        (const float*)d_in[7],  (const float*)d_in[8],
        (const float*)d_in[9],  (const float*)d_in[10],
        (const float*)d_in[11], (const float*)d_in[12],
        (const float*)d_in[13], (const float*)d_in[14],
        (const float*)d_in[15], (const float*)d_in[16],
        (const float*)d_in[17], (const float*)d_in[18],
        outh, outc);
}

// round 8
// speedup vs baseline: 1.4016x; 1.4016x over previous
#include <cuda_runtime.h>
#include <cstdint>

#define THREADS 256
#define EPS 1e-5f
#define SM_B 65536
#define SM_PAR 90112
#define SM_RED 98816
#define SMEM_BYTES 102912

__device__ float g_Wt[163840];

static __device__ __forceinline__ uint32_t s2u(const void* p) {
    uint32_t a;
    asm("{.reg .u64 t; cvta.to.shared.u64 t,%1; cvt.u32.u64 %0,t;}" : "=r"(a) : "l"(p));
    return a;
}
static __device__ __forceinline__ float rna(float x) {
    uint32_t r;
    asm("cvt.rna.tf32.f32 %0,%1;" : "=r"(r) : "f"(x));
    return __uint_as_float(r);
}
static __device__ __forceinline__ float sigm(float x) { return 1.f / (1.f + __expf(-x)); }
static __device__ __forceinline__ float tanh_(float x) { return 2.f / (1.f + __expf(-2.f * x)) - 1.f; }
static __device__ __forceinline__ void cp16(uint32_t dst, const void* src) {
    asm volatile("cp.async.cg.shared.global [%0],[%1],16;" :: "r"(dst), "l"(src));
}
#define CP_COMMIT() asm volatile("cp.async.commit_group;" ::: "memory")
#define CP_WAIT1()  asm volatile("cp.async.wait_group 1;" ::: "memory")

static __device__ __forceinline__ void mma8(float* d, const uint32_t* a, const uint32_t* b) {
    asm volatile(
        "mma.sync.aligned.m16n8k8.row.col.f32.tf32.tf32.f32 "
        "{%0,%1,%2,%3},{%4,%5,%6,%7},{%8,%9},{%0,%1,%2,%3};"
        : "+f"(d[0]), "+f"(d[1]), "+f"(d[2]), "+f"(d[3])
        : "r"(a[0]), "r"(a[1]), "r"(a[2]), "r"(a[3]), "r"(b[0]), "r"(b[1]));
}

// Storage slot sidx holds weight-gate WGm[sidx] so the flat chunk stream
// matches processing order u,i,lf,rf,o.
// g_Wt[sidx][s][t2g][lane][h] = W_cat[k][n], k = s*8+(lane&3)+h*4,
//   n = WGm[sidx]*128 + t2g*8 + (lane>>2)
__global__ void prep_kernel(const float* __restrict__ Wl, const float* __restrict__ Wr) {
    int gid = blockIdx.x * 256 + threadIdx.x;
    int h = gid & 1, lane = (gid >> 1) & 31, t2g = (gid >> 6) & 15, s = (gid >> 10) & 31;
    int sidx = gid >> 15;
    const int WG[5] = {0, 1, 3, 4, 2};
    int g = WG[sidx];
    int k = s * 8 + (lane & 3) + h * 4;
    int n = g * 128 + t2g * 8 + (lane >> 2);
    float w = (k < 128) ? Wl[k * 640 + n] : Wr[(k - 128) * 640 + n];
    g_Wt[gid] = rna(w);
}

// per-row LN stats from fragment regs: quad shuffle + cross-warp redbuf
static __device__ __forceinline__ void rowstats(const float* vals, float* red,
                                                int mc, int nh, int lane,
                                                float* mu_, float* rs_) {
    float s1[4] = {0.f, 0.f, 0.f, 0.f}, s2[4] = {0.f, 0.f, 0.f, 0.f};
    #pragma unroll
    for (int m2 = 0; m2 < 2; m2++)
        #pragma unroll
        for (int t2 = 0; t2 < 4; t2++) {
            const float* d = vals + (m2 * 4 + t2) * 4;
            s1[m2 * 2]     += d[0] + d[1];  s2[m2 * 2]     += d[0] * d[0] + d[1] * d[1];
            s1[m2 * 2 + 1] += d[2] + d[3];  s2[m2 * 2 + 1] += d[2] * d[2] + d[3] * d[3];
        }
    #pragma unroll
    for (int j = 0; j < 4; j++) {
        s1[j] += __shfl_xor_sync(0xffffffffu, s1[j], 1);
        s2[j] += __shfl_xor_sync(0xffffffffu, s2[j], 1);
        s1[j] += __shfl_xor_sync(0xffffffffu, s1[j], 2);
        s2[j] += __shfl_xor_sync(0xffffffffu, s2[j], 2);
    }
    if ((lane & 3) == 0) {
        #pragma unroll
        for (int j = 0; j < 4; j++) {
            int row = mc * 32 + (j >> 1) * 16 + (lane >> 2) + (j & 1) * 8;
            *(float2*)(red + (row * 4 + nh) * 2) = make_float2(s1[j], s2[j]);
        }
    }
    __syncthreads();
    #pragma unroll
    for (int j = 0; j < 4; j++) {
        int row = mc * 32 + (j >> 1) * 16 + (lane >> 2) + (j & 1) * 8;
        float4 p0 = *(const float4*)(red + row * 8);
        float4 p1 = *(const float4*)(red + row * 8 + 4);
        float a = p0.x + p0.z + p1.x + p1.z;
        float b = p0.y + p0.w + p1.y + p1.w;
        float m = a * 0.0078125f;
        mu_[j] = m;
        rs_[j] = rsqrtf(fmaxf(b * 0.0078125f - m * m, 0.f) + EPS);
    }
}

__global__ void __launch_bounds__(THREADS, 2)
lstm_kernel(const float* __restrict__ lh, const float* __restrict__ lcell,
            const float* __restrict__ rh, const float* __restrict__ rcell,
            const float* __restrict__ br,
            const float* __restrict__ gu, const float* __restrict__ bu,
            const float* __restrict__ gi, const float* __restrict__ bi,
            const float* __restrict__ go, const float* __restrict__ bo,
            const float* __restrict__ glf, const float* __restrict__ blf,
            const float* __restrict__ grf, const float* __restrict__ brf,
            const float* __restrict__ gcc, const float* __restrict__ bcc,
            float* __restrict__ outh, float* __restrict__ outc) {
    extern __shared__ char sm[];
    float* smA = (float*)sm;
    float* smB = (float*)(sm + SM_B);
    float* brs = (float*)(sm + SM_PAR);
    float* gsv = brs + 640;
    float* bsv = gsv + 768;
    float* red0 = (float*)(sm + SM_RED);
    float* red1 = red0 + 512;
    const uint32_t smBu = s2u(smB);
    const int tid = threadIdx.x, lane = tid & 31, wid = tid >> 5;
    const int mc = wid & 1, nh = wid >> 1;
    const int tile = blockIdx.x;

    // prologue: cp.async chunks 0,1
    {
        const float4* s0 = (const float4*)g_Wt + tid * 2;
        cp16(smBu + tid * 32, s0); cp16(smBu + tid * 32 + 16, s0 + 1); CP_COMMIT();
        const float4* s1 = (const float4*)(g_Wt + 2048) + tid * 2;
        cp16(smBu + 8192 + tid * 32, s1); cp16(smBu + 8192 + tid * 32 + 16, s1 + 1); CP_COMMIT();
    }
    for (int i = tid; i < 640; i += THREADS) brs[i] = br[i];
    if (tid < 128) {
        gsv[tid] = gu[tid];        bsv[tid] = bu[tid];
        gsv[128 + tid] = gi[tid];  bsv[128 + tid] = bi[tid];
        gsv[256 + tid] = go[tid];  bsv[256 + tid] = bo[tid];
        gsv[384 + tid] = glf[tid]; bsv[384 + tid] = blf[tid];
        gsv[512 + tid] = grf[tid]; bsv[512 + tid] = brf[tid];
        gsv[640 + tid] = gcc[tid]; bsv[640 + tid] = bcc[tid];
    }
    // A = [lh | rh] in A-fragment order, 64 rows
    for (int i = tid; i < 4096; i += THREADS) {
        int r = i >> 6, q = i & 63;
        size_t base = (size_t)(tile * 64 + r) * 128;
        float4 v = (q < 32) ? ((const float4*)(lh + base))[q] : ((const float4*)(rh + base))[q - 32];
        float vv[4] = {rna(v.x), rna(v.y), rna(v.z), rna(v.w)};
        int rl = r & 15, mt = r >> 4;
        #pragma unroll
        for (int e = 0; e < 4; e++) {
            int k = q * 4 + e, s = k >> 3, kk = k & 7;
            int ln = (rl & 7) * 4 + (kk & 3);
            int j = (rl >> 3) + ((kk >> 2) << 1);
            smA[((s * 4 + mt) * 32 + ln) * 4 + j] = vv[e];
        }
    }

    float creg[32], muc[4], rsc[4];
    const int WGm[5] = {0, 1, 3, 4, 2};   // u, i, lf, rf, o
    const int colb = nh * 32 + 2 * (lane & 3);
    int f = 0;
    for (int pg = 0; pg < 5; pg++) {
        const int wg = WGm[pg];
        float acc[32];
        #pragma unroll
        for (int i = 0; i < 32; i++) acc[i] = 0.f;
        for (int cc = 0; cc < 16; cc++, f++) {
            CP_WAIT1();
            __syncthreads();
            if (f + 2 < 80) {
                const float4* src = (const float4*)(g_Wt + (f + 2) * 2048) + tid * 2;
                uint32_t d = smBu + ((f + 2) % 3) * 8192 + tid * 32;
                cp16(d, src); cp16(d + 16, src + 1);
            }
            CP_COMMIT();
            const float* bb = smB + (f % 3) * 2048;
            #pragma unroll
            for (int sl = 0; sl < 2; sl++) {
                int s = cc * 2 + sl;
                uint32_t a[2][4], b[4][2];
                #pragma unroll
                for (int m2 = 0; m2 < 2; m2++) {
                    float4 av = *(const float4*)(smA + ((s * 4 + mc * 2 + m2) * 32 + lane) * 4);
                    a[m2][0] = __float_as_uint(av.x); a[m2][1] = __float_as_uint(av.y);
                    a[m2][2] = __float_as_uint(av.z); a[m2][3] = __float_as_uint(av.w);
                }
                #pragma unroll
                for (int t2 = 0; t2 < 4; t2++) {
                    uint2 bv = *(const uint2*)(bb + ((sl * 16 + nh * 4 + t2) * 32 + lane) * 2);
                    b[t2][0] = bv.x; b[t2][1] = bv.y;
                }
                #pragma unroll
                for (int m2 = 0; m2 < 2; m2++)
                    #pragma unroll
                    for (int t2 = 0; t2 < 4; t2++)
                        mma8(acc + (m2 * 4 + t2) * 4, a[m2], b[t2]);
            }
        }
        // ---- epilogue (fragment domain) ----
        #pragma unroll
        for (int t2 = 0; t2 < 4; t2++) {
            float2 bp = *(const float2*)(brs + wg * 128 + colb + t2 * 8);
            #pragma unroll
            for (int m2 = 0; m2 < 2; m2++) {
                float* d = acc + (m2 * 4 + t2) * 4;
                d[0] += bp.x; d[1] += bp.y; d[2] += bp.x; d[3] += bp.y;
            }
        }
        float cv[32];
        if (pg == 2 || pg == 3) {
            const float* cp_ = (pg == 2) ? lcell : rcell;
            #pragma unroll
            for (int m2 = 0; m2 < 2; m2++)
                #pragma unroll
                for (int t2 = 0; t2 < 4; t2++)
                    #pragma unroll
                    for (int hh = 0; hh < 2; hh++) {
                        int row = mc * 32 + m2 * 16 + (lane >> 2) + hh * 8;
                        float2 c2 = *(const float2*)(cp_ + (size_t)(tile * 64 + row) * 128 + colb + t2 * 8);
                        cv[(m2 * 4 + t2) * 4 + hh * 2]     = c2.x;
                        cv[(m2 * 4 + t2) * 4 + hh * 2 + 1] = c2.y;
                    }
        }
        float mu_[4], rs_[4];
        rowstats(acc, (pg & 1) ? red1 : red0, mc, nh, lane, mu_, rs_);
        const float* GV = gsv + wg * 128;
        const float* BV = bsv + wg * 128;
        if (pg < 4) {
            #pragma unroll
            for (int t2 = 0; t2 < 4; t2++) {
                float2 gp = *(const float2*)(GV + colb + t2 * 8);
                float2 bp = *(const float2*)(BV + colb + t2 * 8);
                #pragma unroll
                for (int m2 = 0; m2 < 2; m2++)
                    #pragma unroll
                    for (int e = 0; e < 4; e++) {
                        int ci = (m2 * 4 + t2) * 4 + e;
                        int j = m2 * 2 + (e >> 1);
                        float x = (acc[ci] - mu_[j]) * rs_[j] * ((e & 1) ? gp.y : gp.x)
                                + ((e & 1) ? bp.y : bp.x);
                        if (pg == 0)      creg[ci] = tanh_(x);
                        else if (pg == 1) creg[ci] *= sigm(x);
                        else              creg[ci] += sigm(x) * cv[ci];
                    }
            }
            if (pg == 3) rowstats(creg, red0, mc, nh, lane, muc, rsc);
        } else {
            const float* GC = gsv + 640;
            const float* BC = bsv + 640;
            #pragma unroll
            for (int t2 = 0; t2 < 4; t2++) {
                float2 gp  = *(const float2*)(GV + colb + t2 * 8);
                float2 bp  = *(const float2*)(BV + colb + t2 * 8);
                float2 gc2 = *(const float2*)(GC + colb + t2 * 8);
                float2 bc2 = *(const float2*)(BC + colb + t2 * 8);
                #pragma unroll
                for (int m2 = 0; m2 < 2; m2++)
                    #pragma unroll
                    for (int hh = 0; hh < 2; hh++) {
                        int row = mc * 32 + m2 * 16 + (lane >> 2) + hh * 8;
                        size_t gb = (size_t)(tile * 64 + row) * 128 + colb + t2 * 8;
                        int j = m2 * 2 + hh;
                        float2 hv, cvo;
                        {
                            int ci = (m2 * 4 + t2) * 4 + hh * 2;
                            float xo = (acc[ci] - mu_[j]) * rs_[j] * gp.x + bp.x;
                            float cl = (creg[ci] - muc[j]) * rsc[j] * gc2.x + bc2.x;
                            hv.x = sigm(xo) * tanh_(cl); cvo.x = cl;
                            xo = (acc[ci + 1] - mu_[j]) * rs_[j] * gp.y + bp.y;
                            cl = (creg[ci + 1] - muc[j]) * rsc[j] * gc2.y + bc2.y;
                            hv.y = sigm(xo) * tanh_(cl); cvo.y = cl;
                        }
                        *(float2*)(outh + gb) = hv;
                        *(float2*)(outc + gb) = cvo;
                    }
            }
        }
    }
}

extern "C" void kernel_launch(void* const* d_in, const int* in_sizes, int n_in,
                              void* d_out, int out_size) {
    const float* lh = (const float*)d_in[0];
    const float* lc = (const float*)d_in[1];
    const float* rh = (const float*)d_in[2];
    const float* rc = (const float*)d_in[3];
    const float* Wl = (const float*)d_in[4];
    const float* Wr = (const float*)d_in[5];
    const float* br = (const float*)d_in[6];
    float* outh = (float*)d_out;
    float* outc = outh + (size_t)131072 * 128;
    cudaFuncSetAttribute(lstm_kernel, cudaFuncAttributeMaxDynamicSharedMemorySize, SMEM_BYTES);
    prep_kernel<<<640, 256>>>(Wl, Wr);
    lstm_kernel<<<2048, THREADS, SMEM_BYTES>>>(
        lh, lc, rh, rc, br,
        (const float*)d_in[7],  (const float*)d_in[8],
        (const float*)d_in[9],  (const float*)d_in[10],
        (const float*)d_in[11], (const float*)d_in[12],
        (const float*)d_in[13], (const float*)d_in[14],
        (const float*)d_in[15], (const float*)d_in[16],
        (const float*)d_in[17], (const float*)d_in[18],
        outh, outc);
}

// round 9
// speedup vs baseline: 1.4435x; 1.0299x over previous
#include <cuda_runtime.h>
#include <cstdint>

#define THREADS 256
#define EPS 1e-5f
#define SM_PAR 65536
#define SM_RED 74240
#define SMEM_BYTES 80384

__device__ float g_Wt[163840];

static __device__ __forceinline__ float rna(float x) {
    uint32_t r;
    asm("cvt.rna.tf32.f32 %0,%1;" : "=r"(r) : "f"(x));
    return __uint_as_float(r);
}
static __device__ __forceinline__ float sigm(float x) { return 1.f / (1.f + __expf(-x)); }
static __device__ __forceinline__ float tanh_(float x) { return 2.f / (1.f + __expf(-2.f * x)) - 1.f; }

static __device__ __forceinline__ void mma8(float* d, const uint32_t* a, const uint32_t* b) {
    asm volatile(
        "mma.sync.aligned.m16n8k8.row.col.f32.tf32.tf32.f32 "
        "{%0,%1,%2,%3},{%4,%5,%6,%7},{%8,%9},{%0,%1,%2,%3};"
        : "+f"(d[0]), "+f"(d[1]), "+f"(d[2]), "+f"(d[3])
        : "r"(a[0]), "r"(a[1]), "r"(a[2]), "r"(a[3]), "r"(b[0]), "r"(b[1]));
}

// Storage slot sidx holds weight-gate WGm[sidx] (processing order u,i,lf,rf,o).
// g_Wt[sidx][s][t2g][lane][h] = W_cat[k][n], k = s*8+(lane&3)+h*4,
//   n = WGm[sidx]*128 + t2g*8 + (lane>>2)
__global__ void prep_kernel(const float* __restrict__ Wl, const float* __restrict__ Wr) {
    int gid = blockIdx.x * 256 + threadIdx.x;
    int h = gid & 1, lane = (gid >> 1) & 31, t2g = (gid >> 6) & 15, s = (gid >> 10) & 31;
    int sidx = gid >> 15;
    const int WG[5] = {0, 1, 3, 4, 2};
    int g = WG[sidx];
    int k = s * 8 + (lane & 3) + h * 4;
    int n = g * 128 + t2g * 8 + (lane >> 2);
    float w = (k < 128) ? Wl[k * 640 + n] : Wr[(k - 128) * 640 + n];
    g_Wt[gid] = rna(w);
}

// per-row LN stats from fragment regs: quad shuffle + cross-warp redbuf
static __device__ __forceinline__ void rowstats(const float* vals, float* red,
                                                int mc, int nh, int lane,
                                                float* mu_, float* rs_) {
    float s1[4] = {0.f, 0.f, 0.f, 0.f}, s2[4] = {0.f, 0.f, 0.f, 0.f};
    #pragma unroll
    for (int m2 = 0; m2 < 2; m2++)
        #pragma unroll
        for (int t2 = 0; t2 < 4; t2++) {
            const float* d = vals + (m2 * 4 + t2) * 4;
            s1[m2 * 2]     += d[0] + d[1];  s2[m2 * 2]     += d[0] * d[0] + d[1] * d[1];
            s1[m2 * 2 + 1] += d[2] + d[3];  s2[m2 * 2 + 1] += d[2] * d[2] + d[3] * d[3];
        }
    #pragma unroll
    for (int j = 0; j < 4; j++) {
        s1[j] += __shfl_xor_sync(0xffffffffu, s1[j], 1);
        s2[j] += __shfl_xor_sync(0xffffffffu, s2[j], 1);
        s1[j] += __shfl_xor_sync(0xffffffffu, s1[j], 2);
        s2[j] += __shfl_xor_sync(0xffffffffu, s2[j], 2);
    }
    if ((lane & 3) == 0) {
        #pragma unroll
        for (int j = 0; j < 4; j++) {
            int row = mc * 32 + (j >> 1) * 16 + (lane >> 2) + (j & 1) * 8;
            *(float2*)(red + (row * 4 + nh) * 2) = make_float2(s1[j], s2[j]);
        }
    }
    __syncthreads();
    #pragma unroll
    for (int j = 0; j < 4; j++) {
        int row = mc * 32 + (j >> 1) * 16 + (lane >> 2) + (j & 1) * 8;
        float4 p0 = *(const float4*)(red + row * 8);
        float4 p1 = *(const float4*)(red + row * 8 + 4);
        float a = p0.x + p0.z + p1.x + p1.z;
        float b = p0.y + p0.w + p1.y + p1.w;
        float m = a * 0.0078125f;
        mu_[j] = m;
        rs_[j] = rsqrtf(fmaxf(b * 0.0078125f - m * m, 0.f) + EPS);
    }
}

__global__ void __launch_bounds__(THREADS, 2)
lstm_kernel(const float* __restrict__ lh, const float* __restrict__ lcell,
            const float* __restrict__ rh, const float* __restrict__ rcell,
            const float* __restrict__ br,
            const float* __restrict__ gu, const float* __restrict__ bu,
            const float* __restrict__ gi, const float* __restrict__ bi,
            const float* __restrict__ go, const float* __restrict__ bo,
            const float* __restrict__ glf, const float* __restrict__ blf,
            const float* __restrict__ grf, const float* __restrict__ brf,
            const float* __restrict__ gcc, const float* __restrict__ bcc,
            float* __restrict__ outh, float* __restrict__ outc) {
    extern __shared__ char sm[];
    float* smA = (float*)sm;
    float* brs = (float*)(sm + SM_PAR);
    float* gsv = brs + 640;
    float* bsv = gsv + 768;
    float* red0 = (float*)(sm + SM_RED);
    float* red1 = red0 + 512;
    float* red2 = red1 + 512;
    const int tid = threadIdx.x, lane = tid & 31, wid = tid >> 5;
    const int mc = wid & 1, nh = wid >> 1;
    const int tile = blockIdx.x;

    for (int i = tid; i < 640; i += THREADS) brs[i] = br[i];
    if (tid < 128) {
        gsv[tid] = gu[tid];        bsv[tid] = bu[tid];
        gsv[128 + tid] = gi[tid];  bsv[128 + tid] = bi[tid];
        gsv[256 + tid] = go[tid];  bsv[256 + tid] = bo[tid];
        gsv[384 + tid] = glf[tid]; bsv[384 + tid] = blf[tid];
        gsv[512 + tid] = grf[tid]; bsv[512 + tid] = brf[tid];
        gsv[640 + tid] = gcc[tid]; bsv[640 + tid] = bcc[tid];
    }
    // A = [lh | rh] in A-fragment order, 64 rows
    for (int i = tid; i < 4096; i += THREADS) {
        int r = i >> 6, q = i & 63;
        size_t base = (size_t)(tile * 64 + r) * 128;
        float4 v = (q < 32) ? ((const float4*)(lh + base))[q] : ((const float4*)(rh + base))[q - 32];
        float vv[4] = {rna(v.x), rna(v.y), rna(v.z), rna(v.w)};
        int rl = r & 15, mt = r >> 4;
        #pragma unroll
        for (int e = 0; e < 4; e++) {
            int k = q * 4 + e, s = k >> 3, kk = k & 7;
            int ln = (rl & 7) * 4 + (kk & 3);
            int j = (rl >> 3) + ((kk >> 2) << 1);
            smA[((s * 4 + mt) * 32 + ln) * 4 + j] = vv[e];
        }
    }
    __syncthreads();

    float creg[32], muc[4], rsc[4];
    const int WGm[5] = {0, 1, 3, 4, 2};   // u, i, lf, rf, o
    const int colb = nh * 32 + 2 * (lane & 3);
    for (int pg = 0; pg < 5; pg++) {
        const int wg = WGm[pg];
        float acc[32];
        #pragma unroll
        for (int i = 0; i < 32; i++) acc[i] = 0.f;
        // barrier-free mainloop: A from smem, B direct LDG.nc from L2
        const float* WB = g_Wt + pg * 32768 + nh * 256 + lane * 2;
        #pragma unroll 4
        for (int s = 0; s < 32; s++) {
            uint32_t a[2][4], b[4][2];
            #pragma unroll
            for (int t2 = 0; t2 < 4; t2++) {
                uint2 bv = __ldg((const uint2*)(WB + s * 1024 + t2 * 64));
                b[t2][0] = bv.x; b[t2][1] = bv.y;
            }
            #pragma unroll
            for (int m2 = 0; m2 < 2; m2++) {
                float4 av = *(const float4*)(smA + ((s * 4 + mc * 2 + m2) * 32 + lane) * 4);
                a[m2][0] = __float_as_uint(av.x); a[m2][1] = __float_as_uint(av.y);
                a[m2][2] = __float_as_uint(av.z); a[m2][3] = __float_as_uint(av.w);
            }
            #pragma unroll
            for (int m2 = 0; m2 < 2; m2++)
                #pragma unroll
                for (int t2 = 0; t2 < 4; t2++)
                    mma8(acc + (m2 * 4 + t2) * 4, a[m2], b[t2]);
        }
        // ---- epilogue (fragment domain) ----
        #pragma unroll
        for (int t2 = 0; t2 < 4; t2++) {
            float2 bp = *(const float2*)(brs + wg * 128 + colb + t2 * 8);
            #pragma unroll
            for (int m2 = 0; m2 < 2; m2++) {
                float* d = acc + (m2 * 4 + t2) * 4;
                d[0] += bp.x; d[1] += bp.y; d[2] += bp.x; d[3] += bp.y;
            }
        }
        float cv[32];
        if (pg == 2 || pg == 3) {
            const float* cp_ = (pg == 2) ? lcell : rcell;
            #pragma unroll
            for (int m2 = 0; m2 < 2; m2++)
                #pragma unroll
                for (int t2 = 0; t2 < 4; t2++)
                    #pragma unroll
                    for (int hh = 0; hh < 2; hh++) {
                        int row = mc * 32 + m2 * 16 + (lane >> 2) + hh * 8;
                        float2 c2 = *(const float2*)(cp_ + (size_t)(tile * 64 + row) * 128 + colb + t2 * 8);
                        cv[(m2 * 4 + t2) * 4 + hh * 2]     = c2.x;
                        cv[(m2 * 4 + t2) * 4 + hh * 2 + 1] = c2.y;
                    }
        }
        float mu_[4], rs_[4];
        rowstats(acc, (pg & 1) ? red1 : red0, mc, nh, lane, mu_, rs_);
        const float* GV = gsv + wg * 128;
        const float* BV = bsv + wg * 128;
        if (pg < 4) {
            #pragma unroll
            for (int t2 = 0; t2 < 4; t2++) {
                float2 gp = *(const float2*)(GV + colb + t2 * 8);
                float2 bp = *(const float2*)(BV + colb + t2 * 8);
                #pragma unroll
                for (int m2 = 0; m2 < 2; m2++)
                    #pragma unroll
                    for (int e = 0; e < 4; e++) {
                        int ci = (m2 * 4 + t2) * 4 + e;
                        int j = m2 * 2 + (e >> 1);
                        float x = (acc[ci] - mu_[j]) * rs_[j] * ((e & 1) ? gp.y : gp.x)
                                + ((e & 1) ? bp.y : bp.x);
                        if (pg == 0)      creg[ci] = tanh_(x);
                        else if (pg == 1) creg[ci] *= sigm(x);
                        else              creg[ci] += sigm(x) * cv[ci];
                    }
            }
            if (pg == 3) rowstats(creg, red2, mc, nh, lane, muc, rsc);
        } else {
            const float* GC = gsv + 640;
            const float* BC = bsv + 640;
            #pragma unroll
            for (int t2 = 0; t2 < 4; t2++) {
                float2 gp  = *(const float2*)(GV + colb + t2 * 8);
                float2 bp  = *(const float2*)(BV + colb + t2 * 8);
                float2 gc2 = *(const float2*)(GC + colb + t2 * 8);
                float2 bc2 = *(const float2*)(BC + colb + t2 * 8);
                #pragma unroll
                for (int m2 = 0; m2 < 2; m2++)
                    #pragma unroll
                    for (int hh = 0; hh < 2; hh++) {
                        int row = mc * 32 + m2 * 16 + (lane >> 2) + hh * 8;
                        size_t gb = (size_t)(tile * 64 + row) * 128 + colb + t2 * 8;
                        int j = m2 * 2 + hh;
                        float2 hv, cvo;
                        {
                            int ci = (m2 * 4 + t2) * 4 + hh * 2;
                            float xo = (acc[ci] - mu_[j]) * rs_[j] * gp.x + bp.x;
                            float cl = (creg[ci] - muc[j]) * rsc[j] * gc2.x + bc2.x;
                            hv.x = sigm(xo) * tanh_(cl); cvo.x = cl;
                            xo = (acc[ci + 1] - mu_[j]) * rs_[j] * gp.y + bp.y;
                            cl = (creg[ci + 1] - muc[j]) * rsc[j] * gc2.y + bc2.y;
                            hv.y = sigm(xo) * tanh_(cl); cvo.y = cl;
                        }
                        *(float2*)(outh + gb) = hv;
                        *(float2*)(outc + gb) = cvo;
                    }
            }
        }
    }
}

extern "C" void kernel_launch(void* const* d_in, const int* in_sizes, int n_in,
                              void* d_out, int out_size) {
    const float* lh = (const float*)d_in[0];
    const float* lc = (const float*)d_in[1];
    const float* rh = (const float*)d_in[2];
    const float* rc = (const float*)d_in[3];
    const float* Wl = (const float*)d_in[4];
    const float* Wr = (const float*)d_in[5];
    const float* br = (const float*)d_in[6];
    float* outh = (float*)d_out;
    float* outc = outh + (size_t)131072 * 128;
    cudaFuncSetAttribute(lstm_kernel, cudaFuncAttributeMaxDynamicSharedMemorySize, SMEM_BYTES);
    prep_kernel<<<640, 256>>>(Wl, Wr);
    lstm_kernel<<<2048, THREADS, SMEM_BYTES>>>(
        lh, lc, rh, rc, br,
        (const float*)d_in[7],  (const float*)d_in[8],
        (const float*)d_in[9],  (const float*)d_in[10],
        (const float*)d_in[11], (const float*)d_in[12],
        (const float*)d_in[13], (const float*)d_in[14],
        (const float*)d_in[15], (const float*)d_in[16],
        (const float*)d_in[17], (const float*)d_in[18],
        outh, outc);
}